// round 12
// baseline (speedup 1.0000x reference)
#include <cuda_runtime.h>
#include <cuda_fp16.h>
#include <cstdint>

#define D     512
#define NH    8
#define HD    64
#define WN    5
#define BATCH 4
#define SEQ   4096
#define MTOT  (BATCH * SEQ)

// ---------------- scratch (static device allocations) ----------------
__device__ __half g_qkv[3ull * MTOT * D];      // q,k,v fp16
__device__ __half g_W[3ull * D * D];           // transposed: [n][k], fp16

// ---------------- PTX helpers ----------------
__device__ __forceinline__ uint32_t smem_u32(const void* p) {
    uint32_t a;
    asm("{ .reg .u64 t; cvta.to.shared.u64 t, %1; cvt.u32.u64 %0, t; }" : "=r"(a) : "l"(p));
    return a;
}
__device__ __forceinline__ void cp16(uint32_t dst, const void* src) {
    asm volatile("cp.async.cg.shared.global [%0], [%1], 16;" :: "r"(dst), "l"(src));
}
#define CP_COMMIT() asm volatile("cp.async.commit_group;" ::: "memory")
#define CP_WAIT(n)  asm volatile("cp.async.wait_group %0;" :: "n"(n) : "memory")

#define LDSM4(r, addr) \
    asm volatile("ldmatrix.sync.aligned.m8n8.x4.shared.b16 {%0,%1,%2,%3}, [%4];" \
        : "=r"((r)[0]), "=r"((r)[1]), "=r"((r)[2]), "=r"((r)[3]) : "r"(addr))

#define MMA_F16(c, a, b) \
    asm volatile("mma.sync.aligned.m16n8k16.row.col.f32.f16.f16.f32 " \
        "{%0,%1,%2,%3},{%4,%5,%6,%7},{%8,%9},{%0,%1,%2,%3};" \
        : "+f"((c)[0]), "+f"((c)[1]), "+f"((c)[2]), "+f"((c)[3]) \
        : "r"((a)[0]), "r"((a)[1]), "r"((a)[2]), "r"((a)[3]), "r"((b)[0]), "r"((b)[1]))

// ---------------- W conversion only (X converted inside the GEMM) ----------------
#define NWBLK ((3 * D * D) / 256)        // 3072 blocks

__global__ __launch_bounds__(256) void convert_w(
    const float* __restrict__ Wq, const float* __restrict__ Wk, const float* __restrict__ Wv)
{
    int idx = blockIdx.x * 256 + threadIdx.x;  // < 3*512*512
    int z = idx >> 18;
    int r = idx & 262143;
    int k = r >> 9;
    int n = r & 511;
    const float* W = (z == 0) ? Wq : (z == 1 ? Wk : Wv);
    g_W[(size_t)z * D * D + (size_t)n * D + k] = __float2half_rn(W[(size_t)k * D + n]);
}

// ---------------- mma.sync GEMM (fp16, BK=64, X converted in-kernel) ----------------
#define BM 128
#define BN 128
#define BK 64
#define NKIT (D / BK)            // 8
#define PADK 72                  // row stride in fp16 (144 B rows -> conflict-free ldmatrix)
#define TILE_BYTES (128 * PADK * 2)          // 18432
#define SOFF_A 0
#define SOFF_B TILE_BYTES
#define STAGE_BYTES (2 * TILE_BYTES)         // 36864
#define GEMM_SMEM (2 * STAGE_BYTES)          // 73728

// A-fragment staging: 4 (row,chunk) pairs per thread, 8 floats each.
__device__ __forceinline__ void ldg_a(
    float4 (&ar)[4][2], const float* __restrict__ X, int m0, int kc, int tid)
{
#pragma unroll
    for (int p = 0; p < 4; ++p) {
        const int q = tid + p * 256;
        const int r = q >> 3, c = q & 7;
        const float* src = X + (size_t)(m0 + r) * D + kc + c * 8;
        ar[p][0] = *reinterpret_cast<const float4*>(src);
        ar[p][1] = *reinterpret_cast<const float4*>(src + 4);
    }
}
__device__ __forceinline__ void sts_a(
    uint32_t base, const float4 (&ar)[4][2], int tid)
{
#pragma unroll
    for (int p = 0; p < 4; ++p) {
        const int q = tid + p * 256;
        const int r = q >> 3, c = q & 7;
        const uint32_t doff = (uint32_t)(r * PADK + c * 8) * 2;
        __half2 h0 = __floats2half2_rn(ar[p][0].x, ar[p][0].y);
        __half2 h1 = __floats2half2_rn(ar[p][0].z, ar[p][0].w);
        __half2 h2 = __floats2half2_rn(ar[p][1].x, ar[p][1].y);
        __half2 h3 = __floats2half2_rn(ar[p][1].z, ar[p][1].w);
        uint4 v;
        v.x = *reinterpret_cast<uint32_t*>(&h0);
        v.y = *reinterpret_cast<uint32_t*>(&h1);
        v.z = *reinterpret_cast<uint32_t*>(&h2);
        v.w = *reinterpret_cast<uint32_t*>(&h3);
        asm volatile("st.shared.v4.b32 [%0], {%1,%2,%3,%4};"
                     :: "r"(base + SOFF_A + doff), "r"(v.x), "r"(v.y), "r"(v.z), "r"(v.w)
                     : "memory");
    }
}
__device__ __forceinline__ void cp_b(
    uint32_t base, const __half* __restrict__ W, int n0, int kc, int tid)
{
#pragma unroll
    for (int p = 0; p < 4; ++p) {
        const int q = tid + p * 256;
        const int r = q >> 3, c = q & 7;
        const uint32_t doff = (uint32_t)(r * PADK + c * 8) * 2;
        cp16(base + SOFF_B + doff, W + (size_t)(n0 + r) * D + kc + c * 8);
    }
}

__global__ __launch_bounds__(256) void qkv_gemm_mma(
    const float* __restrict__ X,
    const float* __restrict__ bq, const float* __restrict__ bk, const float* __restrict__ bv)
{
    extern __shared__ char smem[];
    const uint32_t sb = smem_u32(smem);

    const int tid = threadIdx.x;
    const int wid = tid >> 5;
    const int lane = tid & 31;
    const int warp_m = wid >> 2;      // 0..1
    const int warp_n = wid & 3;       // 0..3

    const int m0 = blockIdx.x * BM;
    const int n0 = blockIdx.y * BN;
    const int z = blockIdx.z;

    const __half* W = g_W + (size_t)z * D * D;
    __half* O = g_qkv + (size_t)z * MTOT * D;
    const float* bias = (z == 0) ? bq : (z == 1 ? bk : bv);

    float acc[4][4][4];
#pragma unroll
    for (int i = 0; i < 4; i++)
#pragma unroll
        for (int j = 0; j < 4; j++)
#pragma unroll
            for (int e = 0; e < 4; e++) acc[i][j][e] = 0.f;

    // prologue: stage 0
    float4 ar[4][2];
    ldg_a(ar, X, m0, 0, tid);
    sts_a(sb, ar, tid);
    cp_b(sb, W, n0, 0, tid);
    CP_COMMIT();

    const int a_row = warp_m * 64 + (lane & 15);
    const int a_colb = ((lane >> 4) << 3);
    const int b_row0 = warp_n * 32 + ((lane >> 4) << 3) + (lane & 7);
    const int b_colb = (((lane >> 3) & 1) << 3);

    for (int kt = 0; kt < NKIT; ++kt) {
        const int buf = kt & 1;
        if (kt + 1 < NKIT) {
            ldg_a(ar, X, m0, (kt + 1) * BK, tid);        // LDG in flight during compute
            cp_b(sb + (buf ^ 1) * STAGE_BYTES, W, n0, (kt + 1) * BK, tid);
            CP_COMMIT();
            CP_WAIT(1);
        } else {
            CP_WAIT(0);
        }
        __syncthreads();

        const uint32_t stg = sb + buf * STAGE_BYTES;
#pragma unroll
        for (int ks = 0; ks < 4; ++ks) {
            uint32_t bf[4][2];
#pragma unroll
            for (int j2 = 0; j2 < 2; ++j2) {
                const int nr = b_row0 + j2 * 16;
                const uint32_t off = (uint32_t)(nr * PADK + ks * 16 + b_colb) * 2;
                uint32_t t[4];
                LDSM4(t, stg + SOFF_B + off);
                bf[2 * j2][0] = t[0]; bf[2 * j2][1] = t[1];
                bf[2 * j2 + 1][0] = t[2]; bf[2 * j2 + 1][1] = t[3];
            }
#pragma unroll
            for (int i = 0; i < 4; ++i) {
                uint32_t af[4];
                const uint32_t off = (uint32_t)((a_row + i * 16) * PADK + ks * 16 + a_colb) * 2;
                LDSM4(af, stg + SOFF_A + off);
#pragma unroll
                for (int j = 0; j < 4; ++j)
                    MMA_F16(acc[i][j], af, bf[j]);
            }
        }
        __syncthreads();

        if (kt + 1 < NKIT)
            sts_a(sb + (buf ^ 1) * STAGE_BYTES, ar, tid);   // convert + store for next stage
    }

    // ---- epilogue: fp16 store with bias (bias added in f32) ----
#pragma unroll
    for (int j = 0; j < 4; ++j) {
        const int ncol = n0 + warp_n * 32 + j * 8 + (lane & 3) * 2;
        const float2 bb = *reinterpret_cast<const float2*>(bias + ncol);
#pragma unroll
        for (int i = 0; i < 4; ++i) {
            const int row0 = m0 + warp_m * 64 + i * 16 + (lane >> 2);
            __half2 v0 = __floats2half2_rn(acc[i][j][0] + bb.x, acc[i][j][1] + bb.y);
            __half2 v1 = __floats2half2_rn(acc[i][j][2] + bb.x, acc[i][j][3] + bb.y);
            *reinterpret_cast<__half2*>(O + (size_t)row0 * D + ncol) = v0;
            *reinterpret_cast<__half2*>(O + (size_t)(row0 + 8) * D + ncol) = v1;
        }
    }
}

// ---------------- attention v8: fp16 qkv, K+V loads in one MLP phase ----------------
__global__ __launch_bounds__(256) void attn_kernel(
    const float* __restrict__ Er,
    const int*   __restrict__ layer_p,
    float* __restrict__ out,
    float* __restrict__ attn_out)
{
    __shared__ float sEr[WN][HD];    // 1.25 KB, shared by all warps (same head)

    const int wlocal = threadIdx.x >> 5;
    const int lane = threadIdx.x & 31;
    const int gw = blockIdx.x * 8 + wlocal;    // 32768 warps total
    const int li = lane & 7;       // dim group within 8-lane token segment
    const int g  = lane >> 3;      // token 0..3 within warp

    const int NCH = SEQ / 4;       // 1024 t-chunks per (b,h)
    const int tc = gw & (NCH - 1);
    const int h  = (gw >> 10) & (NH - 1);
    const int b  = gw >> 13;

    // cooperative Er[h] load: 320 floats
    for (int i = threadIdx.x; i < WN * HD; i += 256) {
        const int w = i / HD, d = i % HD;
        sEr[w][d] = Er[(size_t)(h * HD + d) * WN + w];
    }
    __syncthreads();

    const int dil = 1 << layer_p[0];
    // branch-free shift: h<4 -> 0; h=4..7 -> {-2,-1,1,2}
    const int s = (h < 4) ? 0 : ((h & 3) - 2 + (h >= 6));

    const __half* Qb = g_qkv;
    const __half* Kb = g_qkv + (size_t)MTOT * D;
    const __half* Vb = g_qkv + 2ull * MTOT * D;

    const int t = tc * 4 + g;
    const uint32_t rowbase = (uint32_t)b * SEQ;
    const uint32_t dcol = (uint32_t)(h * HD + li * 8);
    const uint32_t qoff = (rowbase + (uint32_t)t) * D + dcol;   // element index

    // load q (8 halves) -> 8 floats
    const uint4 qr = *reinterpret_cast<const uint4*>(Qb + qoff);
    float qf[8];
    {
        float2 f0 = __half22float2(*reinterpret_cast<const __half2*>(&qr.x));
        float2 f1 = __half22float2(*reinterpret_cast<const __half2*>(&qr.y));
        float2 f2 = __half22float2(*reinterpret_cast<const __half2*>(&qr.z));
        float2 f3 = __half22float2(*reinterpret_cast<const __half2*>(&qr.w));
        qf[0] = f0.x; qf[1] = f0.y; qf[2] = f1.x; qf[3] = f1.y;
        qf[4] = f2.x; qf[5] = f2.y; qf[6] = f3.x; qf[7] = f3.y;
    }

    float lg[WN];
    bool valid[WN];
    uint4 vr[WN];
#pragma unroll
    for (int w = 0; w < WN; ++w) {
        const int tt = t + dil * (s + w - 2);
        const bool ok = (tt >= 0) && (tt < SEQ);
        valid[w] = ok;
        const uint32_t off = (rowbase + (uint32_t)tt) * D + dcol;
        const float4 e0 = *reinterpret_cast<const float4*>(&sEr[w][li * 8]);
        const float4 e1 = *reinterpret_cast<const float4*>(&sEr[w][li * 8 + 4]);
        float part = qf[0] * e0.x + qf[1] * e0.y + qf[2] * e0.z + qf[3] * e0.w
                   + qf[4] * e1.x + qf[5] * e1.y + qf[6] * e1.z + qf[7] * e1.w;
        if (ok) {
            const uint4 kr = *reinterpret_cast<const uint4*>(Kb + off);
            vr[w] = *reinterpret_cast<const uint4*>(Vb + off);   // prefetch V now
            float2 k0 = __half22float2(*reinterpret_cast<const __half2*>(&kr.x));
            float2 k1 = __half22float2(*reinterpret_cast<const __half2*>(&kr.y));
            float2 k2 = __half22float2(*reinterpret_cast<const __half2*>(&kr.z));
            float2 k3 = __half22float2(*reinterpret_cast<const __half2*>(&kr.w));
            part += qf[0] * k0.x + qf[1] * k0.y + qf[2] * k1.x + qf[3] * k1.y
                  + qf[4] * k2.x + qf[5] * k2.y + qf[6] * k3.x + qf[7] * k3.y;
        } else {
            vr[w] = make_uint4(0u, 0u, 0u, 0u);
        }
        part += __shfl_xor_sync(0xffffffffu, part, 1);
        part += __shfl_xor_sync(0xffffffffu, part, 2);
        part += __shfl_xor_sync(0xffffffffu, part, 4);
        lg[w] = ok ? part * 0.125f : -1e30f;
    }

    float mx = lg[0];
#pragma unroll
    for (int w = 1; w < WN; w++) mx = fmaxf(mx, lg[w]);
    float p[WN];
    float sum = 0.f;
#pragma unroll
    for (int w = 0; w < WN; w++) {
        p[w] = valid[w] ? __expf(lg[w] - mx) : 0.f;
        sum += p[w];
    }
    const float inv = 1.f / sum;

    float a0[8] = {0.f, 0.f, 0.f, 0.f, 0.f, 0.f, 0.f, 0.f};
#pragma unroll
    for (int w = 0; w < WN; w++) {
        const float a = p[w];    // scale by inv at the end
        float2 v0 = __half22float2(*reinterpret_cast<const __half2*>(&vr[w].x));
        float2 v1 = __half22float2(*reinterpret_cast<const __half2*>(&vr[w].y));
        float2 v2 = __half22float2(*reinterpret_cast<const __half2*>(&vr[w].z));
        float2 v3 = __half22float2(*reinterpret_cast<const __half2*>(&vr[w].w));
        a0[0] = fmaf(a, v0.x, a0[0]); a0[1] = fmaf(a, v0.y, a0[1]);
        a0[2] = fmaf(a, v1.x, a0[2]); a0[3] = fmaf(a, v1.y, a0[3]);
        a0[4] = fmaf(a, v2.x, a0[4]); a0[5] = fmaf(a, v2.y, a0[5]);
        a0[6] = fmaf(a, v3.x, a0[6]); a0[7] = fmaf(a, v3.y, a0[7]);
    }
    *reinterpret_cast<float4*>(out + qoff) =
        make_float4(a0[0] * inv, a0[1] * inv, a0[2] * inv, a0[3] * inv);
    *reinterpret_cast<float4*>(out + qoff + 4) =
        make_float4(a0[4] * inv, a0[5] * inv, a0[6] * inv, a0[7] * inv);

    if (attn_out != nullptr && li < WN) {
        float a = p[0];
        if (li == 1) a = p[1];
        else if (li == 2) a = p[2];
        else if (li == 3) a = p[3];
        else if (li == 4) a = p[4];
        attn_out[((size_t)((b * NH + h) * SEQ + t)) * WN + li] = a * inv;
    }
}

// ---------------------------------------------------------------------------
extern "C" void kernel_launch(void* const* d_in, const int* in_sizes, int n_in,
                              void* d_out, int out_size)
{
    (void)in_sizes; (void)n_in;
    const float* X  = (const float*)d_in[0];
    const float* Wq = (const float*)d_in[1];
    const float* bq = (const float*)d_in[2];
    const float* Wk = (const float*)d_in[3];
    const float* bk = (const float*)d_in[4];
    const float* Wv = (const float*)d_in[5];
    const float* bv = (const float*)d_in[6];
    const float* Er = (const float*)d_in[7];
    const int* layer = (const int*)d_in[8];

    float* out = (float*)d_out;
    float* attn_out = nullptr;
    const long long OUTN = (long long)MTOT * D;
    const long long ATTN = (long long)BATCH * NH * SEQ * WN;
    if ((long long)out_size >= OUTN + ATTN) attn_out = out + OUTN;

    static bool attr_set = false;
    if (!attr_set) {
        cudaFuncSetAttribute(qkv_gemm_mma, cudaFuncAttributeMaxDynamicSharedMemorySize, GEMM_SMEM);
        attr_set = true;
    }

    convert_w<<<NWBLK, 256>>>(Wq, Wk, Wv);

    dim3 grid(MTOT / BM, D / BN, 3);
    qkv_gemm_mma<<<grid, 256, GEMM_SMEM>>>(X, bq, bk, bv);

    const int nblocks = (BATCH * NH * (SEQ / 4)) / 8;   // 4096 blocks
    attn_kernel<<<nblocks, 256>>>(Er, layer, out, attn_out);
}

// round 13
// speedup vs baseline: 1.1155x; 1.1155x over previous
#include <cuda_runtime.h>
#include <cuda_fp16.h>
#include <cstdint>

#define D     512
#define NH    8
#define HD    64
#define WN    5
#define BATCH 4
#define SEQ   4096
#define MTOT  (BATCH * SEQ)

// ---------------- scratch (static device allocations) ----------------
__device__ __half g_qkv[3ull * MTOT * D];      // q,k,v fp16
__device__ __half g_X[(size_t)MTOT * D];       // X fp16
__device__ __half g_W[3ull * D * D];           // transposed: [n][k], fp16

// ---------------- PTX helpers ----------------
__device__ __forceinline__ uint32_t smem_u32(const void* p) {
    uint32_t a;
    asm("{ .reg .u64 t; cvta.to.shared.u64 t, %1; cvt.u32.u64 %0, t; }" : "=r"(a) : "l"(p));
    return a;
}
__device__ __forceinline__ void cp16(uint32_t dst, const void* src) {
    asm volatile("cp.async.cg.shared.global [%0], [%1], 16;" :: "r"(dst), "l"(src));
}
#define CP_COMMIT() asm volatile("cp.async.commit_group;" ::: "memory")
#define CP_WAIT(n)  asm volatile("cp.async.wait_group %0;" :: "n"(n) : "memory")

#define LDSM4(r, addr) \
    asm volatile("ldmatrix.sync.aligned.m8n8.x4.shared.b16 {%0,%1,%2,%3}, [%4];" \
        : "=r"((r)[0]), "=r"((r)[1]), "=r"((r)[2]), "=r"((r)[3]) : "r"(addr))

#define MMA_F16(c, a, b) \
    asm volatile("mma.sync.aligned.m16n8k16.row.col.f32.f16.f16.f32 " \
        "{%0,%1,%2,%3},{%4,%5,%6,%7},{%8,%9},{%0,%1,%2,%3};" \
        : "+f"((c)[0]), "+f"((c)[1]), "+f"((c)[2]), "+f"((c)[3]) \
        : "r"((a)[0]), "r"((a)[1]), "r"((a)[2]), "r"((a)[3]), "r"((b)[0]), "r"((b)[1]))

// ---------------- fused conversions ----------------
// X: 2048 blocks, 4 float4 per thread. W: 768 blocks, 32x32 smem-tile transpose.
#define NXBLK ((MTOT * D / 4) / 1024)    // 2048
#define NWBLK (3 * 16 * 16)              // 768 tile-blocks (512/32 = 16 per dim)

__global__ __launch_bounds__(256) void convert_all(
    const float* __restrict__ X,
    const float* __restrict__ Wq, const float* __restrict__ Wk, const float* __restrict__ Wv)
{
    __shared__ float ts[32][33];
    const int bid = blockIdx.x;
    if (bid < NXBLK) {
        const size_t base = (size_t)bid * 1024 + threadIdx.x;
        float4 v[4];
#pragma unroll
        for (int p = 0; p < 4; ++p)
            v[p] = reinterpret_cast<const float4*>(X)[base + p * 256];
#pragma unroll
        for (int p = 0; p < 4; ++p) {
            __half2 h0 = make_half2(__float2half_rn(v[p].x), __float2half_rn(v[p].y));
            __half2 h1 = make_half2(__float2half_rn(v[p].z), __float2half_rn(v[p].w));
            uint2 hh;
            hh.x = *reinterpret_cast<uint32_t*>(&h0);
            hh.y = *reinterpret_cast<uint32_t*>(&h1);
            reinterpret_cast<uint2*>(g_X)[base + p * 256] = hh;
        }
    } else {
        const int wb = bid - NXBLK;           // 0..767
        const int z = wb >> 8;                // 256 tiles per z
        const int tile = wb & 255;
        const int k0 = (tile & 15) * 32;
        const int n0 = (tile >> 4) * 32;
        const int tx = threadIdx.x & 31, ty = threadIdx.x >> 5;   // 32 x 8
        const float* W = (z == 0) ? Wq : (z == 1 ? Wk : Wv);
        // coalesced read: ts[k_local][n_local] = W[k0+k_local][n0+n_local]
#pragma unroll
        for (int i = 0; i < 4; ++i)
            ts[ty + 8 * i][tx] = W[(size_t)(k0 + ty + 8 * i) * D + (n0 + tx)];
        __syncthreads();
        // coalesced write: g_W[n0+n_local][k0+k_local], k_local = tx
        __half* dst = g_W + (size_t)z * D * D;
#pragma unroll
        for (int i = 0; i < 4; ++i)
            dst[(size_t)(n0 + ty + 8 * i) * D + (k0 + tx)] =
                __float2half_rn(ts[tx][ty + 8 * i]);
    }
}

// ---------------- mma.sync GEMM (single-pass fp16, BK=64, fp16 out) ----------------
#define BM 128
#define BN 128
#define BK 64
#define NKIT (D / BK)            // 8
#define PADK 72                  // row stride in fp16 (144 B rows -> conflict-free ldmatrix)
#define TILE_BYTES (128 * PADK * 2)          // 18432
#define SOFF_A 0
#define SOFF_B TILE_BYTES
#define STAGE_BYTES (2 * TILE_BYTES)         // 36864
#define GEMM_SMEM (2 * STAGE_BYTES)          // 73728

__device__ __forceinline__ void load_stage(
    uint32_t sb, int stage, int m0, int n0, int kc,
    const __half* __restrict__ W, int tid)
{
    const uint32_t base = sb + stage * STAGE_BYTES;
#pragma unroll
    for (int p = 0; p < 4; ++p) {
        const int q = tid + p * 256;
        const int r = q >> 3, c = q & 7;
        const uint32_t doff = (uint32_t)(r * PADK + c * 8) * 2;
        cp16(base + SOFF_A + doff, g_X + (size_t)(m0 + r) * D + kc + c * 8);
        cp16(base + SOFF_B + doff, W + (size_t)(n0 + r) * D + kc + c * 8);
    }
}

__global__ __launch_bounds__(256, 2) void qkv_gemm_mma(
    const float* __restrict__ bq, const float* __restrict__ bk, const float* __restrict__ bv)
{
    extern __shared__ char smem[];
    const uint32_t sb = smem_u32(smem);

    const int tid = threadIdx.x;
    const int wid = tid >> 5;
    const int lane = tid & 31;
    const int warp_m = wid >> 2;      // 0..1
    const int warp_n = wid & 3;       // 0..3

    const int m0 = blockIdx.x * BM;
    const int n0 = blockIdx.y * BN;
    const int z = blockIdx.z;

    const __half* W = g_W + (size_t)z * D * D;
    __half* O = g_qkv + (size_t)z * MTOT * D;
    const float* bias = (z == 0) ? bq : (z == 1 ? bk : bv);

    float acc[4][4][4];
#pragma unroll
    for (int i = 0; i < 4; i++)
#pragma unroll
        for (int j = 0; j < 4; j++)
#pragma unroll
            for (int e = 0; e < 4; e++) acc[i][j][e] = 0.f;

    load_stage(sb, 0, m0, n0, 0, W, tid);
    CP_COMMIT();

    const int a_row = warp_m * 64 + (lane & 15);
    const int a_colb = ((lane >> 4) << 3);
    const int b_row0 = warp_n * 32 + ((lane >> 4) << 3) + (lane & 7);
    const int b_colb = (((lane >> 3) & 1) << 3);

    for (int kt = 0; kt < NKIT; ++kt) {
        const int buf = kt & 1;
        if (kt + 1 < NKIT) {
            load_stage(sb, buf ^ 1, m0, n0, (kt + 1) * BK, W, tid);
            CP_COMMIT();
            CP_WAIT(1);
        } else {
            CP_WAIT(0);
        }
        __syncthreads();

        const uint32_t stg = sb + buf * STAGE_BYTES;
#pragma unroll
        for (int ks = 0; ks < 4; ++ks) {
            uint32_t bf[4][2];
#pragma unroll
            for (int j2 = 0; j2 < 2; ++j2) {
                const int nr = b_row0 + j2 * 16;
                const uint32_t off = (uint32_t)(nr * PADK + ks * 16 + b_colb) * 2;
                uint32_t t[4];
                LDSM4(t, stg + SOFF_B + off);
                bf[2 * j2][0] = t[0]; bf[2 * j2][1] = t[1];
                bf[2 * j2 + 1][0] = t[2]; bf[2 * j2 + 1][1] = t[3];
            }
#pragma unroll
            for (int i = 0; i < 4; ++i) {
                uint32_t af[4];
                const uint32_t off = (uint32_t)((a_row + i * 16) * PADK + ks * 16 + a_colb) * 2;
                LDSM4(af, stg + SOFF_A + off);
#pragma unroll
                for (int j = 0; j < 4; ++j)
                    MMA_F16(acc[i][j], af, bf[j]);
            }
        }
        __syncthreads();
    }

    // ---- epilogue: fp16 store with bias (bias added in f32) ----
#pragma unroll
    for (int j = 0; j < 4; ++j) {
        const int ncol = n0 + warp_n * 32 + j * 8 + (lane & 3) * 2;
        const float2 bb = *reinterpret_cast<const float2*>(bias + ncol);
#pragma unroll
        for (int i = 0; i < 4; ++i) {
            const int row0 = m0 + warp_m * 64 + i * 16 + (lane >> 2);
            __half2 v0 = __floats2half2_rn(acc[i][j][0] + bb.x, acc[i][j][1] + bb.y);
            __half2 v1 = __floats2half2_rn(acc[i][j][2] + bb.x, acc[i][j][3] + bb.y);
            *reinterpret_cast<__half2*>(O + (size_t)row0 * D + ncol) = v0;
            *reinterpret_cast<__half2*>(O + (size_t)(row0 + 8) * D + ncol) = v1;
        }
    }
}

// ---------------- attention v8: fp16 qkv, K+V loads in one MLP phase ----------------
__global__ __launch_bounds__(256) void attn_kernel(
    const float* __restrict__ Er,
    const int*   __restrict__ layer_p,
    float* __restrict__ out,
    float* __restrict__ attn_out)
{
    __shared__ float sEr[WN][HD];    // 1.25 KB, shared by all warps (same head)

    const int wlocal = threadIdx.x >> 5;
    const int lane = threadIdx.x & 31;
    const int gw = blockIdx.x * 8 + wlocal;    // 32768 warps total
    const int li = lane & 7;       // dim group within 8-lane token segment
    const int g  = lane >> 3;      // token 0..3 within warp

    const int NCH = SEQ / 4;       // 1024 t-chunks per (b,h)
    const int tc = gw & (NCH - 1);
    const int h  = (gw >> 10) & (NH - 1);
    const int b  = gw >> 13;

    // cooperative Er[h] load: 320 floats
    for (int i = threadIdx.x; i < WN * HD; i += 256) {
        const int w = i / HD, d = i % HD;
        sEr[w][d] = Er[(size_t)(h * HD + d) * WN + w];
    }
    __syncthreads();

    const int dil = 1 << layer_p[0];
    // branch-free shift: h<4 -> 0; h=4..7 -> {-2,-1,1,2}
    const int s = (h < 4) ? 0 : ((h & 3) - 2 + (h >= 6));

    const __half* Qb = g_qkv;
    const __half* Kb = g_qkv + (size_t)MTOT * D;
    const __half* Vb = g_qkv + 2ull * MTOT * D;

    const int t = tc * 4 + g;
    const uint32_t rowbase = (uint32_t)b * SEQ;
    const uint32_t dcol = (uint32_t)(h * HD + li * 8);
    const uint32_t qoff = (rowbase + (uint32_t)t) * D + dcol;   // element index

    // load q (8 halves) -> 8 floats
    const uint4 qr = *reinterpret_cast<const uint4*>(Qb + qoff);
    float qf[8];
    {
        float2 f0 = __half22float2(*reinterpret_cast<const __half2*>(&qr.x));
        float2 f1 = __half22float2(*reinterpret_cast<const __half2*>(&qr.y));
        float2 f2 = __half22float2(*reinterpret_cast<const __half2*>(&qr.z));
        float2 f3 = __half22float2(*reinterpret_cast<const __half2*>(&qr.w));
        qf[0] = f0.x; qf[1] = f0.y; qf[2] = f1.x; qf[3] = f1.y;
        qf[4] = f2.x; qf[5] = f2.y; qf[6] = f3.x; qf[7] = f3.y;
    }

    float lg[WN];
    bool valid[WN];
    uint4 vr[WN];
#pragma unroll
    for (int w = 0; w < WN; ++w) {
        const int tt = t + dil * (s + w - 2);
        const bool ok = (tt >= 0) && (tt < SEQ);
        valid[w] = ok;
        const uint32_t off = (rowbase + (uint32_t)tt) * D + dcol;
        const float4 e0 = *reinterpret_cast<const float4*>(&sEr[w][li * 8]);
        const float4 e1 = *reinterpret_cast<const float4*>(&sEr[w][li * 8 + 4]);
        float part = qf[0] * e0.x + qf[1] * e0.y + qf[2] * e0.z + qf[3] * e0.w
                   + qf[4] * e1.x + qf[5] * e1.y + qf[6] * e1.z + qf[7] * e1.w;
        if (ok) {
            const uint4 kr = *reinterpret_cast<const uint4*>(Kb + off);
            vr[w] = *reinterpret_cast<const uint4*>(Vb + off);   // prefetch V now
            float2 k0 = __half22float2(*reinterpret_cast<const __half2*>(&kr.x));
            float2 k1 = __half22float2(*reinterpret_cast<const __half2*>(&kr.y));
            float2 k2 = __half22float2(*reinterpret_cast<const __half2*>(&kr.z));
            float2 k3 = __half22float2(*reinterpret_cast<const __half2*>(&kr.w));
            part += qf[0] * k0.x + qf[1] * k0.y + qf[2] * k1.x + qf[3] * k1.y
                  + qf[4] * k2.x + qf[5] * k2.y + qf[6] * k3.x + qf[7] * k3.y;
        } else {
            vr[w] = make_uint4(0u, 0u, 0u, 0u);
        }
        part += __shfl_xor_sync(0xffffffffu, part, 1);
        part += __shfl_xor_sync(0xffffffffu, part, 2);
        part += __shfl_xor_sync(0xffffffffu, part, 4);
        lg[w] = ok ? part * 0.125f : -1e30f;
    }

    float mx = lg[0];
#pragma unroll
    for (int w = 1; w < WN; w++) mx = fmaxf(mx, lg[w]);
    float p[WN];
    float sum = 0.f;
#pragma unroll
    for (int w = 0; w < WN; w++) {
        p[w] = valid[w] ? __expf(lg[w] - mx) : 0.f;
        sum += p[w];
    }
    const float inv = 1.f / sum;

    float a0[8] = {0.f, 0.f, 0.f, 0.f, 0.f, 0.f, 0.f, 0.f};
#pragma unroll
    for (int w = 0; w < WN; w++) {
        const float a = p[w];    // scale by inv at the end
        float2 v0 = __half22float2(*reinterpret_cast<const __half2*>(&vr[w].x));
        float2 v1 = __half22float2(*reinterpret_cast<const __half2*>(&vr[w].y));
        float2 v2 = __half22float2(*reinterpret_cast<const __half2*>(&vr[w].z));
        float2 v3 = __half22float2(*reinterpret_cast<const __half2*>(&vr[w].w));
        a0[0] = fmaf(a, v0.x, a0[0]); a0[1] = fmaf(a, v0.y, a0[1]);
        a0[2] = fmaf(a, v1.x, a0[2]); a0[3] = fmaf(a, v1.y, a0[3]);
        a0[4] = fmaf(a, v2.x, a0[4]); a0[5] = fmaf(a, v2.y, a0[5]);
        a0[6] = fmaf(a, v3.x, a0[6]); a0[7] = fmaf(a, v3.y, a0[7]);
    }
    *reinterpret_cast<float4*>(out + qoff) =
        make_float4(a0[0] * inv, a0[1] * inv, a0[2] * inv, a0[3] * inv);
    *reinterpret_cast<float4*>(out + qoff + 4) =
        make_float4(a0[4] * inv, a0[5] * inv, a0[6] * inv, a0[7] * inv);

    if (attn_out != nullptr && li < WN) {
        float a = p[0];
        if (li == 1) a = p[1];
        else if (li == 2) a = p[2];
        else if (li == 3) a = p[3];
        else if (li == 4) a = p[4];
        attn_out[((size_t)((b * NH + h) * SEQ + t)) * WN + li] = a * inv;
    }
}

// ---------------------------------------------------------------------------
extern "C" void kernel_launch(void* const* d_in, const int* in_sizes, int n_in,
                              void* d_out, int out_size)
{
    (void)in_sizes; (void)n_in;
    const float* X  = (const float*)d_in[0];
    const float* Wq = (const float*)d_in[1];
    const float* bq = (const float*)d_in[2];
    const float* Wk = (const float*)d_in[3];
    const float* bk = (const float*)d_in[4];
    const float* Wv = (const float*)d_in[5];
    const float* bv = (const float*)d_in[6];
    const float* Er = (const float*)d_in[7];
    const int* layer = (const int*)d_in[8];

    float* out = (float*)d_out;
    float* attn_out = nullptr;
    const long long OUTN = (long long)MTOT * D;
    const long long ATTN = (long long)BATCH * NH * SEQ * WN;
    if ((long long)out_size >= OUTN + ATTN) attn_out = out + OUTN;

    static bool attr_set = false;
    if (!attr_set) {
        cudaFuncSetAttribute(qkv_gemm_mma, cudaFuncAttributeMaxDynamicSharedMemorySize, GEMM_SMEM);
        attr_set = true;
    }

    convert_all<<<NXBLK + NWBLK, 256>>>(X, Wq, Wk, Wv);

    dim3 grid(MTOT / BM, D / BN, 3);
    qkv_gemm_mma<<<grid, 256, GEMM_SMEM>>>(bq, bk, bv);

    const int nblocks = (BATCH * NH * (SEQ / 4)) / 8;   // 4096 blocks
    attn_kernel<<<nblocks, 256>>>(Er, layer, out, attn_out);
}